// round 2
// baseline (speedup 1.0000x reference)
#include <cuda_runtime.h>
#include <stdint.h>

// Problem constants (fixed shapes per setup_inputs)
#define BATCH 4
#define NPTS  2048
#define NB    (BATCH * NPTS)        // 8192 (b,n) pairs
#define GRID_DIM 64                 // coords in [0,64)
#define BITMAP_WORDS (GRID_DIM * GRID_DIM * GRID_DIM / 32)  // 8192 words / batch
#define PRIOR_VOX 4096              // 16^3
#define OCC_K 26
#define OCC_BASE ((size_t)NB * PRIOR_VOX)   // 33,554,432

// Scratch: per-batch occupancy bitmap (4 * 32KB = 128KB). Static __device__ per rules.
__device__ unsigned int g_bitmap[BATCH * BITMAP_WORDS];

// 26 neighbor offsets; first 6 are the face offsets (order matches reference).
__constant__ int8_t c_noff[26][3] = {
    {-1,0,0},{1,0,0},{0,-1,0},{0,1,0},{0,0,-1},{0,0,1},
    {-1,-1,0},{-1,1,0},{1,-1,0},{1,1,0},
    {-1,0,-1},{-1,0,1},{1,0,-1},{1,0,1},
    {0,-1,-1},{0,-1,1},{0,1,-1},{0,1,1},
    {-1,-1,-1},{-1,-1,1},{-1,1,-1},{-1,1,1},
    {1,-1,-1},{1,-1,1},{1,1,-1},{1,1,1}};

__global__ void zero_bitmap_kernel() {
    int t = blockIdx.x * blockDim.x + threadIdx.x;
    if (t < BATCH * BITMAP_WORDS) g_bitmap[t] = 0u;
}

__global__ void build_bitmap_kernel(const int* __restrict__ coords) {
    int t = blockIdx.x * blockDim.x + threadIdx.x;
    if (t >= NB) return;
    int b = t >> 11;                       // t / NPTS
    int x = coords[t * 3 + 0];
    int y = coords[t * 3 + 1];
    int z = coords[t * 3 + 2];
    int idx = (x << 12) | (y << 6) | z;    // x*4096 + y*64 + z
    atomicOr(&g_bitmap[b * BITMAP_WORDS + (idx >> 5)], 1u << (idx & 31));
}

// One CTA per (b,n). 256 threads. Warp 0 probes 26 neighbors (writes occ,
// ballots face mask); all threads stream 4096 floats of prior with fully
// contiguous warp-wide float4 stores.
__global__ __launch_bounds__(256, 8)
void prior_occ_kernel(const int* __restrict__ coords, float* __restrict__ out) {
    const int bn = blockIdx.x;
    const int b  = bn >> 11;
    const int t  = threadIdx.x;

    __shared__ unsigned s_mask;

    const int x = coords[bn * 3 + 0];
    const int y = coords[bn * 3 + 1];
    const int z = coords[bn * 3 + 2];

    if (t < 32) {
        bool present = false;
        if (t < OCC_K) {
            int nx = x + c_noff[t][0];
            int ny = y + c_noff[t][1];
            int nz = z + c_noff[t][2];
            if ((unsigned)nx < GRID_DIM && (unsigned)ny < GRID_DIM &&
                (unsigned)nz < GRID_DIM) {
                int idx = (nx << 12) | (ny << 6) | nz;
                present = (g_bitmap[b * BITMAP_WORDS + (idx >> 5)] >> (idx & 31)) & 1u;
            }
            out[OCC_BASE + (size_t)bn * OCC_K + t] = present ? 1.0f : 0.0f;
        }
        unsigned bal = __ballot_sync(0xffffffffu, present);
        if (t == 0) s_mask = bal;
    }
    __syncthreads();

    const unsigned m = s_mask;
    const float r15 = 1.0f / 15.0f;
    float* out_p = out + (size_t)bn * PRIOR_VOX;

    // Voxel v = i*256 + j*16 + k; dists = [i/15, 1-i/15, j/15, 1-j/15, k/15, 1-k/15]
    // prior[v] = min over faces f of (has_nb[f] ? 1.0 : dist[f])
    // Each thread emits float4 at v = t*4 + q*1024 -> warp store = 512B contiguous.
    #pragma unroll
    for (int q = 0; q < 4; q++) {
        int v  = (t << 2) + (q << 10);
        int i  = v >> 8;
        int j  = (v >> 4) & 15;
        int k0 = v & 15;               // multiple of 4 within a row of 16
        float gx = (float)i * r15;
        float gy = (float)j * r15;
        float base = 1.0f;
        if (!(m & 1u))  base = fminf(base, gx);
        if (!(m & 2u))  base = fminf(base, 1.0f - gx);
        if (!(m & 4u))  base = fminf(base, gy);
        if (!(m & 8u))  base = fminf(base, 1.0f - gy);
        float4 r;
        float* rp = &r.x;
        #pragma unroll
        for (int kk = 0; kk < 4; kk++) {
            float gz = (float)(k0 + kk) * r15;
            float val = base;
            if (!(m & 16u)) val = fminf(val, gz);
            if (!(m & 32u)) val = fminf(val, 1.0f - gz);
            rp[kk] = val;
        }
        *reinterpret_cast<float4*>(out_p + v) = r;
    }
}

extern "C" void kernel_launch(void* const* d_in, const int* in_sizes, int n_in,
                              void* d_out, int out_size) {
    const int* coords = (const int*)d_in[0];
    float* out = (float*)d_out;

    zero_bitmap_kernel<<<(BATCH * BITMAP_WORDS + 255) / 256, 256>>>();
    build_bitmap_kernel<<<(NB + 255) / 256, 256>>>(coords);
    prior_occ_kernel<<<NB, 256>>>(coords, out);
}